// round 17
// baseline (speedup 1.0000x reference)
#include <cuda_runtime.h>
#include <cuda_bf16.h>
#include <cstdint>

static constexpr int BATCH = 8;
static constexpr int LQ    = 2048;
static constexpr int LKV   = 2048;
static constexpr int DIM   = 128;   // D == DV == 128
static constexpr float SM_SCALE = 0.08838834764831845f; // 1/sqrt(128)

// Scratch (device globals; no runtime allocation allowed)
__device__ __align__(128) float g_Qt[(size_t)BATCH * LQ  * DIM];   // tf32 bits
__device__ __align__(128) float g_Kt[(size_t)BATCH * LKV * DIM];   // tf32 bits
__device__ __align__(128) float g_Vt[(size_t)BATCH * DIM * LKV];   // V^T, tf32 bits

// ---------------------------------------------------------------------------
// Helpers
// ---------------------------------------------------------------------------
__device__ __forceinline__ uint32_t smem_u32(const void* p) {
    uint32_t a;
    asm("{ .reg .u64 t; cvta.to.shared.u64 t, %1; cvt.u32.u64 %0, t; }"
        : "=r"(a) : "l"(p));
    return a;
}
__device__ __forceinline__ uint32_t f2tf(float f) {
    uint32_t r;
    asm("cvt.rna.tf32.f32 %0, %1;" : "=r"(r) : "f"(f));
    return r;
}
__device__ __forceinline__ uint32_t lds_u32(uint32_t a) {
    uint32_t v;
    asm volatile("ld.shared.b32 %0, [%1];" : "=r"(v) : "r"(a));
    return v;
}
__device__ __forceinline__ void sts_f32x2(uint32_t a, float x, float y) {
    asm volatile("st.shared.v2.f32 [%0], {%1,%2};" :: "r"(a), "f"(x), "f"(y) : "memory");
}
__device__ __forceinline__ void mma_tf32(float* d, const uint32_t* a, const uint32_t* b) {
    asm volatile("mma.sync.aligned.m16n8k8.row.col.f32.tf32.tf32.f32 "
                 "{%0,%1,%2,%3}, {%4,%5,%6,%7}, {%8,%9}, {%0,%1,%2,%3};"
                 : "+f"(d[0]), "+f"(d[1]), "+f"(d[2]), "+f"(d[3])
                 : "r"(a[0]), "r"(a[1]), "r"(a[2]), "r"(a[3]), "r"(b[0]), "r"(b[1]));
}
#define CP_ASYNC16(dst, src) \
    asm volatile("cp.async.cg.shared.global [%0], [%1], 16;" :: "r"(dst), "l"(src) : "memory")
#define CP_COMMIT()  asm volatile("cp.async.commit_group;" ::: "memory")
#define CP_WAIT(n)   asm volatile("cp.async.wait_group %0;" :: "n"(n) : "memory")

// ---------------------------------------------------------------------------
// Prep A: elementwise tf32 truncation of Q and K into scratch
// ---------------------------------------------------------------------------
__global__ __launch_bounds__(256) void qk_tf32_kernel(
    const float* __restrict__ Q, const float* __restrict__ K)
{
    const size_t t = (size_t)blockIdx.x * 256 + threadIdx.x;   // float4 index
    const bool isK = blockIdx.y != 0;
    const float4 v = ((const float4*)(isK ? K : Q))[t];
    uint4 o = make_uint4(f2tf(v.x), f2tf(v.y), f2tf(v.z), f2tf(v.w));
    ((uint4*)(isK ? g_Kt : g_Qt))[t] = o;
}

// ---------------------------------------------------------------------------
// Prep B: transpose V and pre-truncate to tf32:  V[b][k][n] -> g_Vt[b][n][k]
// ---------------------------------------------------------------------------
__global__ __launch_bounds__(256) void vt_tf32_kernel(const float* __restrict__ V)
{
    __shared__ float t[32][33];
    const int b  = blockIdx.z;
    const int k0 = blockIdx.y * 32;
    const int n0 = blockIdx.x * 32;
    const int tx = threadIdx.x & 31;
    const int ty = threadIdx.x >> 5;   // 0..7

    #pragma unroll
    for (int i = 0; i < 4; i++) {
        int k = ty + i * 8;
        t[k][tx] = V[((size_t)b * LKV + k0 + k) * DIM + n0 + tx];
    }
    __syncthreads();
    #pragma unroll
    for (int i = 0; i < 4; i++) {
        int n = ty + i * 8;
        uint32_t bits = f2tf(t[tx][n]);
        *(uint32_t*)&g_Vt[((size_t)b * DIM + n0 + n) * LKV + k0 + tx] = bits;
    }
}

// ---------------------------------------------------------------------------
// Fused attention: per CTA (64-row Q tile, one batch):
//   Sweep 1 over 32 KV-chunks of 64: S = Q Kc^T (tf32), E = tf32(exp(S*scale))
//     staged in smem, C += E Vc^T; exact row sums accumulated locally.
//   Reduce row sums -> inv[64].
//   Sweep 2: recompute E per chunk (deterministic), STG W = E*inv.
//   Epilogue: STG C*inv.
// No E through gmem; no inter-kernel dependency beyond preps.
//
// smem rows padded +4 floats => conflict-free fragment LDS (bank = 4g+cc).
// K/V double buffered; prefetch issued after the barrier that proves the
// target stage is no longer being read (pattern race-checked per sweep).
// ---------------------------------------------------------------------------
static constexpr int QROWB = 528;   // 128 + 4 floats
static constexpr int VROWB = 272;   // 64 + 4 floats
static constexpr uint32_t OQ  = 0;            // Q    64 x 528  = 33792
static constexpr uint32_t OK0 = 33792;        // K s0 64 x 528  = 33792
static constexpr uint32_t OK1 = 67584;        // K s1
static constexpr uint32_t OV0 = 101376;       // V s0 128 x 272 = 34816
static constexpr uint32_t OV1 = 136192;       // V s1
static constexpr uint32_t OE  = 171008;       // E    64 x 272  = 17408
static constexpr uint32_t ORD = 188416;       // red  4 x 64 floats = 1024
static constexpr uint32_t OIV = 189440;       // inv  64 floats = 256
static constexpr int F_SMEM = 189696 + 1024;

__global__ __launch_bounds__(256, 1) void fused_attn_kernel(
    float* __restrict__ W, float* __restrict__ C)
{
    extern __shared__ char smem[];
    const uint32_t sb = (smem_u32(smem) + 1023u) & ~1023u;
    const uint32_t SQ = sb + OQ;
    const uint32_t SK0 = sb + OK0, SK1 = sb + OK1;
    const uint32_t SV0 = sb + OV0, SV1 = sb + OV1;
    const uint32_t SE = sb + OE;
    float* red   = (float*)(smem + (sb - smem_u32(smem)) + ORD);   // [4][64]
    float* inv_s = (float*)(smem + (sb - smem_u32(smem)) + OIV);   // [64]

    const int tid  = threadIdx.x;
    const int lane = tid & 31;
    const int w    = tid >> 5;
    const int wm   = (w >> 2) * 32;   // 2 warp-rows (M)
    const int wni  = w & 3;           // 4 warp-cols
    const int wn1  = wni * 16;        // MMA1 N offset (S is 64x64)
    const int wn2  = wni * 32;        // MMA2 N offset (C is 64x128)

    const int m0 = blockIdx.x * 64;
    const int b  = blockIdx.y;

    const float* Qg = g_Qt + ((size_t)b * LQ + m0) * DIM;
    const float* Kg = g_Kt + (size_t)b * LKV * DIM;
    const float* Vg = g_Vt + (size_t)b * DIM * LKV;
    float* Wb = W + ((size_t)b * LQ + m0) * LKV;
    float* Cb = C + ((size_t)b * LQ + m0) * DIM;

    const uint32_t g   = lane >> 2;   // 0..7
    const uint32_t cc4 = lane & 3;    // 0..3
    const int er = lane >> 2;
    const int ec = (lane & 3) * 2;

    // ---- load Q tile once (64 x 128 floats = 2048 16B units) ----
    #pragma unroll
    for (int i = 0; i < 8; i++) {
        int u = i * 256 + tid;
        int row = u >> 5, un = (u & 31) * 16;
        CP_ASYNC16(SQ + (uint32_t)row * QROWB + un, Qg + (size_t)row * DIM + (un >> 2));
    }
    CP_COMMIT();

    auto load_k = [&](int c, uint32_t KS) {
        const int n0c = c * 64;
        #pragma unroll
        for (int i = 0; i < 8; i++) {
            int u = i * 256 + tid;
            int row = u >> 5, un = (u & 31) * 16;
            CP_ASYNC16(KS + (uint32_t)row * QROWB + un,
                       Kg + (size_t)(n0c + row) * DIM + (un >> 2));
        }
    };
    auto load_v = [&](int c, uint32_t VS) {
        const int k0c = c * 64;
        #pragma unroll
        for (int i = 0; i < 8; i++) {
            int u = i * 256 + tid;
            int row = u >> 4, un = (u & 15) * 16;
            CP_ASYNC16(VS + (uint32_t)row * VROWB + un,
                       Vg + (size_t)row * LKV + k0c + (un >> 2));
        }
    };

    float accC[2][4][4] = {};
    float rs[2][2] = {{0.f, 0.f}, {0.f, 0.f}};

    load_k(0, SK0); load_v(0, SV0); CP_COMMIT();

    // ================= Sweep 1 =================
    for (int c = 0; c < 32; c++) {
        CP_WAIT(0);
        __syncthreads();   // chunk data ready; E-stage + other stage released

        if (c < 31) {
            load_k(c + 1, ((c + 1) & 1) ? SK1 : SK0);
            load_v(c + 1, ((c + 1) & 1) ? SV1 : SV0);
            CP_COMMIT();
        }
        const uint32_t KS = (c & 1) ? SK1 : SK0;
        const uint32_t VS = (c & 1) ? SV1 : SV0;

        // MMA1: S(64x64) = Q(64x128) Kc(64x128)^T ; warp tile 32x16
        float sacc[2][2][4] = {};
        #pragma unroll
        for (int ks = 0; ks < 16; ks++) {
            const uint32_t kb = ks * 8;
            uint32_t A[2][4], B[2][2];
            #pragma unroll
            for (int mf = 0; mf < 2; mf++) {
                uint32_t a0 = SQ + (uint32_t)(wm + mf * 16 + g) * QROWB + (kb + cc4) * 4;
                A[mf][0] = lds_u32(a0);
                A[mf][1] = lds_u32(a0 + 8 * QROWB);
                A[mf][2] = lds_u32(a0 + 16);
                A[mf][3] = lds_u32(a0 + 8 * QROWB + 16);
            }
            #pragma unroll
            for (int nf = 0; nf < 2; nf++) {
                uint32_t b0 = KS + (uint32_t)(wn1 + nf * 8 + g) * QROWB + (kb + cc4) * 4;
                B[nf][0] = lds_u32(b0);
                B[nf][1] = lds_u32(b0 + 16);
            }
            #pragma unroll
            for (int mf = 0; mf < 2; mf++)
                #pragma unroll
                for (int nf = 0; nf < 2; nf++)
                    mma_tf32(sacc[mf][nf], A[mf], B[nf]);
        }

        // exp -> tf32 round -> stage E + accumulate row sums
        #pragma unroll
        for (int mf = 0; mf < 2; mf++)
            #pragma unroll
            for (int nf = 0; nf < 2; nf++) {
                float e0 = __uint_as_float(f2tf(__expf(fminf(sacc[mf][nf][0] * SM_SCALE, 80.f))));
                float e1 = __uint_as_float(f2tf(__expf(fminf(sacc[mf][nf][1] * SM_SCALE, 80.f))));
                float e2 = __uint_as_float(f2tf(__expf(fminf(sacc[mf][nf][2] * SM_SCALE, 80.f))));
                float e3 = __uint_as_float(f2tf(__expf(fminf(sacc[mf][nf][3] * SM_SCALE, 80.f))));
                uint32_t col = (uint32_t)(wn1 + nf * 8 + ec) * 4;
                uint32_t r0 = SE + (uint32_t)(wm + mf * 16 + er) * VROWB + col;
                sts_f32x2(r0, e0, e1);
                sts_f32x2(r0 + 8 * VROWB, e2, e3);
                rs[mf][0] += e0 + e1;
                rs[mf][1] += e2 + e3;
            }
        __syncthreads();   // E staged, visible to all warps of this M-group

        // MMA2: C(64x128) += E(64x64) Vc^T ; warp tile 32x32, 8 k-steps
        #pragma unroll
        for (int ks = 0; ks < 8; ks++) {
            const uint32_t kb = ks * 8;
            uint32_t A2[2][4], B2[4][2];
            #pragma unroll
            for (int mf = 0; mf < 2; mf++) {
                uint32_t a0 = SE + (uint32_t)(wm + mf * 16 + g) * VROWB + (kb + cc4) * 4;
                A2[mf][0] = lds_u32(a0);
                A2[mf][1] = lds_u32(a0 + 8 * VROWB);
                A2[mf][2] = lds_u32(a0 + 16);
                A2[mf][3] = lds_u32(a0 + 8 * VROWB + 16);
            }
            #pragma unroll
            for (int nf = 0; nf < 4; nf++) {
                uint32_t b0 = VS + (uint32_t)(wn2 + nf * 8 + g) * VROWB + (kb + cc4) * 4;
                B2[nf][0] = lds_u32(b0);
                B2[nf][1] = lds_u32(b0 + 16);
            }
            #pragma unroll
            for (int mf = 0; mf < 2; mf++)
                #pragma unroll
                for (int nf = 0; nf < 4; nf++)
                    mma_tf32(accC[mf][nf], A2[mf], B2[nf]);
        }
    }

    // ---- row-sum reduction (ordered, deterministic) ----
    #pragma unroll
    for (int mf = 0; mf < 2; mf++)
        #pragma unroll
        for (int h = 0; h < 2; h++) {
            float v = rs[mf][h];
            v += __shfl_xor_sync(0xffffffffu, v, 1);
            v += __shfl_xor_sync(0xffffffffu, v, 2);
            if ((lane & 3) == 0)
                red[wni * 64 + wm + mf * 16 + h * 8 + er] = v;
        }
    __syncthreads();
    if (tid < 64)
        inv_s[tid] = 1.0f / (red[tid] + red[64 + tid] + red[128 + tid] + red[192 + tid]);
    __syncthreads();

    // ================= Sweep 2: recompute E, write W = E*inv =================
    load_k(0, SK0); CP_COMMIT();
    for (int c = 0; c < 32; c++) {
        CP_WAIT(0);
        __syncthreads();

        if (c < 31) { load_k(c + 1, ((c + 1) & 1) ? SK1 : SK0); CP_COMMIT(); }
        const uint32_t KS = (c & 1) ? SK1 : SK0;

        float sacc[2][2][4] = {};
        #pragma unroll
        for (int ks = 0; ks < 16; ks++) {
            const uint32_t kb = ks * 8;
            uint32_t A[2][4], B[2][2];
            #pragma unroll
            for (int mf = 0; mf < 2; mf++) {
                uint32_t a0 = SQ + (uint32_t)(wm + mf * 16 + g) * QROWB + (kb + cc4) * 4;
                A[mf][0] = lds_u32(a0);
                A[mf][1] = lds_u32(a0 + 8 * QROWB);
                A[mf][2] = lds_u32(a0 + 16);
                A[mf][3] = lds_u32(a0 + 8 * QROWB + 16);
            }
            #pragma unroll
            for (int nf = 0; nf < 2; nf++) {
                uint32_t b0 = KS + (uint32_t)(wn1 + nf * 8 + g) * QROWB + (kb + cc4) * 4;
                B[nf][0] = lds_u32(b0);
                B[nf][1] = lds_u32(b0 + 16);
            }
            #pragma unroll
            for (int mf = 0; mf < 2; mf++)
                #pragma unroll
                for (int nf = 0; nf < 2; nf++)
                    mma_tf32(sacc[mf][nf], A[mf], B[nf]);
        }

        const int n0c = c * 64;
        #pragma unroll
        for (int mf = 0; mf < 2; mf++) {
            float i0 = inv_s[wm + mf * 16 + er];
            float i1 = inv_s[wm + mf * 16 + er + 8];
            #pragma unroll
            for (int nf = 0; nf < 2; nf++) {
                float e0 = __uint_as_float(f2tf(__expf(fminf(sacc[mf][nf][0] * SM_SCALE, 80.f))));
                float e1 = __uint_as_float(f2tf(__expf(fminf(sacc[mf][nf][1] * SM_SCALE, 80.f))));
                float e2 = __uint_as_float(f2tf(__expf(fminf(sacc[mf][nf][2] * SM_SCALE, 80.f))));
                float e3 = __uint_as_float(f2tf(__expf(fminf(sacc[mf][nf][3] * SM_SCALE, 80.f))));
                int r = wm + mf * 16 + er;
                int nn = n0c + wn1 + nf * 8 + ec;
                *(float2*)(Wb + (size_t)r * LKV + nn)       = make_float2(e0 * i0, e1 * i0);
                *(float2*)(Wb + (size_t)(r + 8) * LKV + nn) = make_float2(e2 * i1, e3 * i1);
            }
        }
    }

    // ---- context epilogue ----
    #pragma unroll
    for (int mf = 0; mf < 2; mf++) {
        float i0 = inv_s[wm + mf * 16 + er];
        float i1 = inv_s[wm + mf * 16 + er + 8];
        #pragma unroll
        for (int nf = 0; nf < 4; nf++) {
            int r = wm + mf * 16 + er;
            int nn = wn2 + nf * 8 + ec;
            *(float2*)(Cb + (size_t)r * DIM + nn) =
                make_float2(accC[mf][nf][0] * i0, accC[mf][nf][1] * i0);
            *(float2*)(Cb + (size_t)(r + 8) * DIM + nn) =
                make_float2(accC[mf][nf][2] * i1, accC[mf][nf][3] * i1);
        }
    }
}

// ---------------------------------------------------------------------------
extern "C" void kernel_launch(void* const* d_in, const int* in_sizes, int n_in,
                              void* d_out, int out_size)
{
    const float* Q = (const float*)d_in[0];
    const float* K = (const float*)d_in[1];
    const float* V = (const float*)d_in[2];

    float* Wout = (float*)d_out;                            // (B,LQ,LKV)
    float* Cout = Wout + (size_t)BATCH * LQ * LKV;          // (B,LQ,DV)

    static bool attr_done = false;
    if (!attr_done) {
        cudaFuncSetAttribute(fused_attn_kernel,
            cudaFuncAttributeMaxDynamicSharedMemorySize, F_SMEM);
        attr_done = true;
    }

    dim3 gq((unsigned)((size_t)BATCH * LQ * DIM / 4 / 256), 2);
    qk_tf32_kernel<<<gq, 256>>>(Q, K);

    dim3 gt(DIM / 32, LKV / 32, BATCH);
    vt_tf32_kernel<<<gt, 256>>>(V);

    dim3 gf(LQ / 64, BATCH);                // 32 x 8 = 256 CTAs
    fused_attn_kernel<<<gf, 256, F_SMEM>>>(Wout, Cout);
}